// round 4
// baseline (speedup 1.0000x reference)
#include <cuda_runtime.h>
#include <cuda_bf16.h>

// Piecewise-linear log-sigmoid approximation (table interp), GB300 sm_103a.
// vals: [64,2048,2048] fp32, x/y: 65-entry uniform tables.
//   x[i] = -10 + i*0.3125 (step 5/16, exact in fp32)
//   idx  = clamp((int)(v*3.2 + 32), 0, 63)
//   out  = v                          if v <  x[0]
//          0                          if v >= x[64]
//          y[i] + (v - x[i])*slope[i] otherwise
//
// R3: persistent grid-stride (148*8 blocks) + conflict-free per-lane
//     replicated tables + V4=4 per iter (regs ~32, occ ~83%).
//     Target ~297us (HBM r+w wall).

#define NBP 65
#define NSEG 64
#define THREADS 256
#define V4_PER_ITER 4                         // float4s per thread per tile
#define TILE_F4 (THREADS * V4_PER_ITER)       // 1024 float4s per block-tile
#define NBLOCKS (148 * 8)

__global__ __launch_bounds__(THREADS)
void logsig_pwl_kernel(const float4* __restrict__ in4,
                       const float*  __restrict__ xt,
                       const float*  __restrict__ yt,
                       float4* __restrict__ out4,
                       int numTiles)
{
    // Per-lane replicated tables: [idx*32 + lane] -> bank == lane always.
    __shared__ float  s_tab[2 * NSEG * 32];   // [0..2047]=y_lo, [2048..4095]=slope
    __shared__ float2 s_seg0[NSEG];
    __shared__ float  s_bounds[2];

    const int tid  = threadIdx.x;
    const int lane = tid & 31;

    if (tid < NSEG) {
        float xl = xt[tid], xh = xt[tid + 1];
        float yl = yt[tid], yh = yt[tid + 1];
        s_seg0[tid] = make_float2(yl, (yh - yl) / (xh - xl));
    }
    if (tid == 0) { s_bounds[0] = xt[0]; s_bounds[1] = xt[NBP - 1]; }
    __syncthreads();

    #pragma unroll
    for (int e = tid; e < NSEG * 32; e += THREADS) {
        float2 seg = s_seg0[e >> 5];
        s_tab[e] = seg.x;
        s_tab[e + NSEG * 32] = seg.y;
    }
    __syncthreads();

    const float x_lo_bound = s_bounds[0];   // -10
    const float x_hi_bound = s_bounds[1];   // +10
    const float INV_H = 3.2f;
    const float OFFS  = 32.0f;
    const float H     = 0.3125f;            // 5/16, exact
    const float X0    = -10.0f;

    const float* tab_l = s_tab + lane;      // lane-private bank stripe

    // Persistent loop over tiles. n4 fits in int32 (67M), so tile math is int.
    for (int t = blockIdx.x; t < numTiles; t += NBLOCKS) {
        int base = t * TILE_F4 + tid;

        float4 v[V4_PER_ITER];
        #pragma unroll
        for (int j = 0; j < V4_PER_ITER; j++)
            v[j] = __ldcs(&in4[base + j * THREADS]);

        #pragma unroll
        for (int j = 0; j < V4_PER_ITER; j++) {
            float vv[4] = {v[j].x, v[j].y, v[j].z, v[j].w};
            float r[4];
            #pragma unroll
            for (int k = 0; k < 4; k++) {
                float val = vv[k];
                int idx = (int)fmaf(val, INV_H, OFFS);
                idx = max(0, min(idx, NSEG - 1));
                int a = idx << 5;
                float yl = tab_l[a];                    // conflict-free LDS
                float m  = tab_l[a + NSEG * 32];        // conflict-free LDS
                float x_lo = fmaf((float)idx, H, X0);   // exact == xt[idx]
                float interp = fmaf(val - x_lo, m, yl);
                r[k] = (val <  x_lo_bound) ? val
                     : (val >= x_hi_bound) ? 0.0f
                     : interp;
            }
            float4 o; o.x = r[0]; o.y = r[1]; o.z = r[2]; o.w = r[3];
            __stcs(&out4[base + j * THREADS], o);
        }
    }
}

// Tail kernel: scalar, handles [start, n) elements.
__global__ void logsig_pwl_tail(const float* __restrict__ vals,
                                const float* __restrict__ xt,
                                const float* __restrict__ yt,
                                float* __restrict__ out,
                                long long start, long long n)
{
    long long i = start + (long long)blockIdx.x * blockDim.x + threadIdx.x;
    if (i >= n) return;
    float x0 = xt[0];
    float xK = xt[NBP - 1];
    float val = vals[i];
    int idx = (int)fmaf(val, 3.2f, 32.0f);
    idx = max(0, min(idx, NSEG - 1));
    float x_lo = xt[idx];
    float y_lo = yt[idx];
    float slope = (yt[idx + 1] - y_lo) / (xt[idx + 1] - x_lo);
    float interp = fmaf(val - x_lo, slope, y_lo);
    out[i] = (val < x0) ? val : (val >= xK) ? 0.0f : interp;
}

extern "C" void kernel_launch(void* const* d_in, const int* in_sizes, int n_in,
                              void* d_out, int out_size)
{
    const float* vals = (const float*)d_in[0];
    const float* xt   = (const float*)d_in[1];
    const float* yt   = (const float*)d_in[2];
    float* out        = (float*)d_out;

    long long n  = (long long)in_sizes[0];
    long long n4 = n / 4;

    long long numTiles = n4 / TILE_F4;
    long long covered  = numTiles * TILE_F4 * 4;   // elements done by main kernel

    if (numTiles > 0) {
        unsigned blocks = (numTiles < NBLOCKS) ? (unsigned)numTiles : NBLOCKS;
        logsig_pwl_kernel<<<blocks, THREADS>>>(
            (const float4*)vals, xt, yt, (float4*)out, (int)numTiles);
    }
    if (covered < n) {
        long long rem = n - covered;
        int tblocks = (int)((rem + 255) / 256);
        logsig_pwl_tail<<<tblocks, 256>>>(vals, xt, yt, out, covered, n);
    }
}

// round 5
// speedup vs baseline: 1.1289x; 1.1289x over previous
#include <cuda_runtime.h>
#include <cuda_bf16.h>

// Piecewise-linear log-sigmoid approximation (table interp), GB300 sm_103a.
// vals: [64,2048,2048] fp32, x/y: 65-entry uniform tables.
//   x[i] = -10 + i*0.3125 (step 5/16, exact in fp32)
//   idx  = clamp((int)(v*3.2 + 32), 0, 63)
//   out  = v                          if v <  x[0]
//          0                          if v >= x[64]
//          y[i] + (v - x[i])*slope[i] otherwise
//
// R4: R1's best-measured structure (flat launch, V4=4, 256 thr, float2 table,
//     plain LDG.128) minus all in-loop predication/64-bit index math.
//     Main kernel covers an exact tile multiple; tail kernel handles rem.
//     We sit on the B300 LTS streaming cap (~6.9-7.0 TB/s); target ~304us.

#define NBP 65
#define NSEG 64
#define THREADS 256
#define V4_PER_THREAD 4                       // float4s per thread
#define TILE_F4 (THREADS * V4_PER_THREAD)     // 1024 float4s per block

__global__ __launch_bounds__(THREADS)
void logsig_pwl_kernel(const float4* __restrict__ in4,
                       const float*  __restrict__ xt,
                       const float*  __restrict__ yt,
                       float4* __restrict__ out4)
{
    __shared__ float2 s_seg[NSEG];      // (y_lo, slope) per segment
    __shared__ float  s_bounds[2];

    const int tid = threadIdx.x;
    if (tid < NSEG) {
        float xl = xt[tid], xh = xt[tid + 1];
        float yl = yt[tid], yh = yt[tid + 1];
        s_seg[tid] = make_float2(yl, (yh - yl) / (xh - xl));
    }
    if (tid == 0) { s_bounds[0] = xt[0]; s_bounds[1] = xt[NBP - 1]; }
    __syncthreads();

    const float x_lo_bound = s_bounds[0];   // -10
    const float x_hi_bound = s_bounds[1];   // +10
    const float INV_H = 3.2f;
    const float OFFS  = 32.0f;
    const float H     = 0.3125f;            // 5/16, exact
    const float X0    = -10.0f;

    // Exact-tile addressing: every access in range by construction (int32 ok:
    // max index = 67,108,863 < 2^31).
    unsigned base = blockIdx.x * TILE_F4 + tid;

    // Front-batched loads -> 4 LDG.128 in flight per thread.
    float4 v[V4_PER_THREAD];
    #pragma unroll
    for (int j = 0; j < V4_PER_THREAD; j++)
        v[j] = in4[base + j * THREADS];

    #pragma unroll
    for (int j = 0; j < V4_PER_THREAD; j++) {
        float vv[4] = {v[j].x, v[j].y, v[j].z, v[j].w};
        float r[4];
        #pragma unroll
        for (int k = 0; k < 4; k++) {
            float val = vv[k];
            int idx = (int)fmaf(val, INV_H, OFFS);
            idx = max(0, min(idx, NSEG - 1));
            float2 seg = s_seg[idx];                 // one LDS.64
            float x_lo = fmaf((float)idx, H, X0);    // exact, matches xt[idx]
            float interp = fmaf(val - x_lo, seg.y, seg.x);
            r[k] = (val <  x_lo_bound) ? val
                 : (val >= x_hi_bound) ? 0.0f
                 : interp;
        }
        float4 o; o.x = r[0]; o.y = r[1]; o.z = r[2]; o.w = r[3];
        out4[base + j * THREADS] = o;
    }
}

// Tail kernel: scalar, handles [start, n) elements (not hit for this shape).
__global__ void logsig_pwl_tail(const float* __restrict__ vals,
                                const float* __restrict__ xt,
                                const float* __restrict__ yt,
                                float* __restrict__ out,
                                long long start, long long n)
{
    long long i = start + (long long)blockIdx.x * blockDim.x + threadIdx.x;
    if (i >= n) return;
    float x0 = xt[0];
    float xK = xt[NBP - 1];
    float val = vals[i];
    int idx = (int)fmaf(val, 3.2f, 32.0f);
    idx = max(0, min(idx, NSEG - 1));
    float x_lo = xt[idx];
    float y_lo = yt[idx];
    float slope = (yt[idx + 1] - y_lo) / (xt[idx + 1] - x_lo);
    float interp = fmaf(val - x_lo, slope, y_lo);
    out[i] = (val < x0) ? val : (val >= xK) ? 0.0f : interp;
}

extern "C" void kernel_launch(void* const* d_in, const int* in_sizes, int n_in,
                              void* d_out, int out_size)
{
    const float* vals = (const float*)d_in[0];
    const float* xt   = (const float*)d_in[1];
    const float* yt   = (const float*)d_in[2];
    float* out        = (float*)d_out;

    long long n  = (long long)in_sizes[0];
    long long n4 = n / 4;

    long long fullBlocks = n4 / TILE_F4;
    long long covered    = fullBlocks * TILE_F4 * 4;   // elements by main kernel

    if (fullBlocks > 0) {
        logsig_pwl_kernel<<<(unsigned)fullBlocks, THREADS>>>(
            (const float4*)vals, xt, yt, (float4*)out);
    }
    if (covered < n) {
        long long rem = n - covered;
        int tblocks = (int)((rem + 255) / 256);
        logsig_pwl_tail<<<tblocks, 256>>>(vals, xt, yt, out, covered, n);
    }
}